// round 1
// baseline (speedup 1.0000x reference)
#include <cuda_runtime.h>
#include <math.h>

#define NCLS 1000
#define BATCH 1024
#define BETA 0.7f
#define LAMBDA1 3.0f
#define CLIP_EPS 1e-4f
#define NTHREADS 256
#define PER_THREAD 4   // 256*4 = 1024 >= 1000

// loss partial accumulators: [0] = sum of CE, [1] = sum of ELR
__device__ float g_acc[2];

__global__ void init_acc_kernel() {
    g_acc[0] = 0.0f;
    g_acc[1] = 0.0f;
}

// block-wide reduction (sum if SUM=true else max), result broadcast to all threads
template <bool SUM>
__device__ __forceinline__ float block_reduce(float val, float* sred) {
    // warp reduce
    #pragma unroll
    for (int o = 16; o > 0; o >>= 1) {
        float other = __shfl_xor_sync(0xFFFFFFFFu, val, o);
        val = SUM ? (val + other) : fmaxf(val, other);
    }
    int lane = threadIdx.x & 31;
    int warp = threadIdx.x >> 5;
    if (lane == 0) sred[warp] = val;
    __syncthreads();
    if (warp == 0) {
        val = (lane < (NTHREADS / 32)) ? sred[lane] : (SUM ? 0.0f : -INFINITY);
        #pragma unroll
        for (int o = 4; o > 0; o >>= 1) {
            float other = __shfl_xor_sync(0xFFFFFFFFu, val, o);
            val = SUM ? (val + other) : fmaxf(val, other);
        }
        if (lane == 0) sred[0] = val;
    }
    __syncthreads();
    float r = sred[0];
    __syncthreads();   // protect sred before next reuse
    return r;
}

// One block per batch row.
__global__ __launch_bounds__(NTHREADS) void elr_row_kernel(
    const float* __restrict__ logits,   // [BATCH, NCLS]
    const float* __restrict__ target,   // [200000, NCLS]
    const int*   __restrict__ label,    // [BATCH]
    const int*   __restrict__ index_p,  // [1]
    float*       __restrict__ new_target, // d_out + 1 (or nullptr)
    int write_target)
{
    __shared__ float sred[32];
    const int row = blockIdx.x;
    const int tid = threadIdx.x;
    const float* x = logits + (size_t)row * NCLS;

    // load logits (guarded)
    float v[PER_THREAD];
    #pragma unroll
    for (int k = 0; k < PER_THREAD; k++) {
        int i = tid + k * NTHREADS;
        v[k] = (i < NCLS) ? x[i] : -INFINITY;
    }

    // 1) max
    float m = v[0];
    #pragma unroll
    for (int k = 1; k < PER_THREAD; k++) m = fmaxf(m, v[k]);
    m = block_reduce<false>(m, sred);

    // 2) sum of exp
    float e[PER_THREAD];
    float lsum = 0.0f;
    #pragma unroll
    for (int k = 0; k < PER_THREAD; k++) {
        int i = tid + k * NTHREADS;
        e[k] = (i < NCLS) ? expf(v[k] - m) : 0.0f;
        lsum += e[k];
    }
    const float sumexp = block_reduce<true>(lsum, sred);
    const float inv_sumexp = 1.0f / sumexp;

    // 3) y_pred = clip(softmax), and its sum for renormalization
    float yp[PER_THREAD];
    float lclip = 0.0f;
    #pragma unroll
    for (int k = 0; k < PER_THREAD; k++) {
        int i = tid + k * NTHREADS;
        if (i < NCLS) {
            float p = e[k] * inv_sumexp;
            p = fminf(fmaxf(p, CLIP_EPS), 1.0f - CLIP_EPS);
            yp[k] = p;
            lclip += p;
        } else {
            yp[k] = 0.0f;
        }
    }
    const float sclip = block_reduce<true>(lclip, sred);
    const float inv_sclip = 1.0f / sclip;

    // 4) EMA row update + dot(new_row, y_pred)
    const int start = index_p[0] * BATCH;
    const float* trow = target + (size_t)(start + row) * NCLS;
    float* drow = write_target ? (new_target + (size_t)(start + row) * NCLS) : nullptr;

    float ldot = 0.0f;
    #pragma unroll
    for (int k = 0; k < PER_THREAD; k++) {
        int i = tid + k * NTHREADS;
        if (i < NCLS) {
            float yn = yp[k] * inv_sclip;
            float nr = BETA * trow[i] + (1.0f - BETA) * yn;
            if (write_target) drow[i] = nr;
            ldot += nr * yp[k];
        }
    }
    const float dot = block_reduce<true>(ldot, sred);

    // 5) CE + ELR partials
    if (tid == 0) {
        const int lab = label[row];
        const float logp_lab = x[lab] - m - logf(sumexp);
        const float ce = -logp_lab;
        const float elr = logf(1.0f - dot);
        atomicAdd(&g_acc[0], ce);
        atomicAdd(&g_acc[1], elr);
    }
}

__global__ void finalize_kernel(float* __restrict__ out) {
    out[0] = g_acc[0] * (1.0f / BATCH) + LAMBDA1 * (g_acc[1] * (1.0f / BATCH));
}

extern "C" void kernel_launch(void* const* d_in, const int* in_sizes, int n_in,
                              void* d_out, int out_size) {
    const float* logits = (const float*)d_in[0];
    const float* target = (const float*)d_in[1];
    const int*   label  = (const int*)d_in[2];
    const int*   index  = (const int*)d_in[3];
    float* out = (float*)d_out;

    const size_t tgt_elems = (size_t)in_sizes[1];   // 200,000,000
    const int write_target = (out_size > 1) ? 1 : 0;

    if (write_target) {
        // bulk copy of the unchanged target into the output slot (rows to be
        // updated are overwritten afterwards by elr_row_kernel — same stream,
        // so ordering is guaranteed)
        cudaMemcpyAsync(out + 1, target, tgt_elems * sizeof(float),
                        cudaMemcpyDeviceToDevice, 0);
    }

    init_acc_kernel<<<1, 1>>>();
    elr_row_kernel<<<BATCH, NTHREADS>>>(logits, target, label, index,
                                        write_target ? (out + 1) : nullptr,
                                        write_target);
    finalize_kernel<<<1, 1>>>(out);
}

// round 2
// speedup vs baseline: 1.9038x; 1.9038x over previous
#include <cuda_runtime.h>
#include <math.h>

#define NCLS 1000
#define BATCH 1024
#define BETA 0.7f
#define LAMBDA1 3.0f
#define CLIP_EPS 1e-4f
#define NTHREADS 256
#define PER_THREAD 4   // 256*4 = 1024 >= 1000

// loss partial accumulators: [0] = sum of CE, [1] = sum of ELR
__device__ float g_acc[2];

__global__ void init_acc_kernel() {
    g_acc[0] = 0.0f;
    g_acc[1] = 0.0f;
}

// ---------------------------------------------------------------------------
// Shifted bulk copy: dst is 4B-misaligned relative to 16B (dst = out+1).
// Strategy: scalar head of 3 floats so that (dst+3) is 16B-aligned, then
// 16B-aligned STG.128 stores fed by 4x LDG.32 loads, scalar tail.
// ---------------------------------------------------------------------------
#define CP_BLOCKS  1184   // 148 SMs * 8
#define CP_THREADS 256

__global__ __launch_bounds__(CP_THREADS) void copy_shift_kernel(
    const float* __restrict__ src, float* __restrict__ dst, long long n)
{
    const long long gid    = (long long)blockIdx.x * CP_THREADS + threadIdx.x;
    const long long stride = (long long)gridDim.x * CP_THREADS;

    // head: first 3 floats (makes dst+3 16B-aligned, given dst = base+1 float
    // with base 256B-aligned)
    if (gid < 3) dst[gid] = src[gid];

    const long long nvec = (n - 3) >> 2;          // number of float4 stores
    float4* __restrict__ dst4 = (float4*)(dst + 3);
    const float* __restrict__ srcs = src + 3;

    for (long long v = gid; v < nvec; v += stride) {
        const float* s = srcs + (v << 2);
        float4 val;
        val.x = __ldcs(s + 0);
        val.y = __ldcs(s + 1);
        val.z = __ldcs(s + 2);
        val.w = __ldcs(s + 3);
        __stcs(dst4 + v, val);
    }

    // tail
    const long long tail_start = 3 + (nvec << 2);
    for (long long i = tail_start + gid; i < n; i += stride) {
        dst[i] = src[i];
    }
}

// block-wide reduction (sum if SUM=true else max), result broadcast to all threads
template <bool SUM>
__device__ __forceinline__ float block_reduce(float val, float* sred) {
    #pragma unroll
    for (int o = 16; o > 0; o >>= 1) {
        float other = __shfl_xor_sync(0xFFFFFFFFu, val, o);
        val = SUM ? (val + other) : fmaxf(val, other);
    }
    int lane = threadIdx.x & 31;
    int warp = threadIdx.x >> 5;
    if (lane == 0) sred[warp] = val;
    __syncthreads();
    if (warp == 0) {
        val = (lane < (NTHREADS / 32)) ? sred[lane] : (SUM ? 0.0f : -INFINITY);
        #pragma unroll
        for (int o = 4; o > 0; o >>= 1) {
            float other = __shfl_xor_sync(0xFFFFFFFFu, val, o);
            val = SUM ? (val + other) : fmaxf(val, other);
        }
        if (lane == 0) sred[0] = val;
    }
    __syncthreads();
    float r = sred[0];
    __syncthreads();
    return r;
}

// One block per batch row.
__global__ __launch_bounds__(NTHREADS) void elr_row_kernel(
    const float* __restrict__ logits,   // [BATCH, NCLS]
    const float* __restrict__ target,   // [200000, NCLS]
    const int*   __restrict__ label,    // [BATCH]
    const int*   __restrict__ index_p,  // [1]
    float*       __restrict__ new_target, // d_out + 1 (or nullptr)
    int write_target)
{
    __shared__ float sred[32];
    const int row = blockIdx.x;
    const int tid = threadIdx.x;
    const float* x = logits + (size_t)row * NCLS;

    float v[PER_THREAD];
    #pragma unroll
    for (int k = 0; k < PER_THREAD; k++) {
        int i = tid + k * NTHREADS;
        v[k] = (i < NCLS) ? x[i] : -INFINITY;
    }

    // 1) max
    float m = v[0];
    #pragma unroll
    for (int k = 1; k < PER_THREAD; k++) m = fmaxf(m, v[k]);
    m = block_reduce<false>(m, sred);

    // 2) sum of exp
    float e[PER_THREAD];
    float lsum = 0.0f;
    #pragma unroll
    for (int k = 0; k < PER_THREAD; k++) {
        int i = tid + k * NTHREADS;
        e[k] = (i < NCLS) ? expf(v[k] - m) : 0.0f;
        lsum += e[k];
    }
    const float sumexp = block_reduce<true>(lsum, sred);
    const float inv_sumexp = 1.0f / sumexp;

    // 3) y_pred = clip(softmax), and its sum for renormalization
    float yp[PER_THREAD];
    float lclip = 0.0f;
    #pragma unroll
    for (int k = 0; k < PER_THREAD; k++) {
        int i = tid + k * NTHREADS;
        if (i < NCLS) {
            float p = e[k] * inv_sumexp;
            p = fminf(fmaxf(p, CLIP_EPS), 1.0f - CLIP_EPS);
            yp[k] = p;
            lclip += p;
        } else {
            yp[k] = 0.0f;
        }
    }
    const float sclip = block_reduce<true>(lclip, sred);
    const float inv_sclip = 1.0f / sclip;

    // 4) EMA row update + dot(new_row, y_pred)
    const int start = index_p[0] * BATCH;
    const float* trow = target + (size_t)(start + row) * NCLS;
    float* drow = write_target ? (new_target + (size_t)(start + row) * NCLS) : nullptr;

    float ldot = 0.0f;
    #pragma unroll
    for (int k = 0; k < PER_THREAD; k++) {
        int i = tid + k * NTHREADS;
        if (i < NCLS) {
            float yn = yp[k] * inv_sclip;
            float nr = BETA * trow[i] + (1.0f - BETA) * yn;
            if (write_target) drow[i] = nr;
            ldot += nr * yp[k];
        }
    }
    const float dot = block_reduce<true>(ldot, sred);

    // 5) CE + ELR partials
    if (tid == 0) {
        const int lab = label[row];
        const float logp_lab = x[lab] - m - logf(sumexp);
        const float ce = -logp_lab;
        const float elr = logf(1.0f - dot);
        atomicAdd(&g_acc[0], ce);
        atomicAdd(&g_acc[1], elr);
    }
}

__global__ void finalize_kernel(float* __restrict__ out) {
    out[0] = g_acc[0] * (1.0f / BATCH) + LAMBDA1 * (g_acc[1] * (1.0f / BATCH));
}

extern "C" void kernel_launch(void* const* d_in, const int* in_sizes, int n_in,
                              void* d_out, int out_size) {
    const float* logits = (const float*)d_in[0];
    const float* target = (const float*)d_in[1];
    const int*   label  = (const int*)d_in[2];
    const int*   index  = (const int*)d_in[3];
    float* out = (float*)d_out;

    const long long tgt_elems = (long long)in_sizes[1];   // 200,000,000
    const int write_target = (out_size > 1) ? 1 : 0;

    if (write_target) {
        copy_shift_kernel<<<CP_BLOCKS, CP_THREADS>>>(target, out + 1, tgt_elems);
    }

    init_acc_kernel<<<1, 1>>>();
    elr_row_kernel<<<BATCH, NTHREADS>>>(logits, target, label, index,
                                        write_target ? (out + 1) : nullptr,
                                        write_target);
    finalize_kernel<<<1, 1>>>(out);
}